// round 2
// baseline (speedup 1.0000x reference)
#include <cuda_runtime.h>
#include <cstdint>

#define NMAX 30000

// ---------------- scratch (no allocation allowed) ----------------
__device__ float g_h [NMAX * 768];   // projected feats, [N][t][256]
__device__ float g_x1[NMAX * 256];   // layer-0 output
__device__ float g_x2[NMAX * 256];   // layer-1 output
__device__ float g_el[NMAX * 12];    // [N][t][head]
__device__ float g_er[NMAX * 12];
__device__ float g_h2[NMAX * 6];     // layer-2 projected [N][t][2]

// ---------------- GEMM: C[N,768] = X[N,K] @ {W_t[K,256]} ----------------
// blockIdx.y in [0,6): 128-col tile. etype = y/2, within-etype colbase = (y&1)*128.
#define BM 128
#define BN 128
#define BK 8

__global__ __launch_bounds__(256) void sgemm_etype(
    const float* __restrict__ X, const float* __restrict__ W,
    float* __restrict__ C, int M, int K)
{
    __shared__ float As[BK][BM];
    __shared__ float Bs[BK][BN];

    const int tid  = threadIdx.x;
    const int row0 = blockIdx.x * BM;
    const int ct   = blockIdx.y;
    const int t    = ct >> 1;
    const int colbase = (ct & 1) * 128;
    const float* Wt = W + (size_t)t * K * 256;

    const int tx = tid & 15, ty = tid >> 4;

    float acc[8][8];
    #pragma unroll
    for (int i = 0; i < 8; i++)
        #pragma unroll
        for (int j = 0; j < 8; j++) acc[i][j] = 0.0f;

    const int arow = tid >> 1;            // 0..127
    const int akq  = (tid & 1) * 4;       // 0 or 4
    const int bk   = tid >> 5;            // 0..7
    const int bc   = (tid & 31) * 4;      // 0..124

    for (int k0 = 0; k0 < K; k0 += BK) {
        float4 av = make_float4(0.f, 0.f, 0.f, 0.f);
        const int gr = row0 + arow;
        if (gr < M)
            av = *reinterpret_cast<const float4*>(X + (size_t)gr * K + k0 + akq);
        As[akq + 0][arow] = av.x;
        As[akq + 1][arow] = av.y;
        As[akq + 2][arow] = av.z;
        As[akq + 3][arow] = av.w;

        float4 bv = *reinterpret_cast<const float4*>(
            Wt + (size_t)(k0 + bk) * 256 + colbase + bc);
        *reinterpret_cast<float4*>(&Bs[bk][bc]) = bv;

        __syncthreads();

        #pragma unroll
        for (int k = 0; k < BK; k++) {
            float4 a0 = *reinterpret_cast<float4*>(&As[k][ty * 8]);
            float4 a1 = *reinterpret_cast<float4*>(&As[k][ty * 8 + 4]);
            float4 b0 = *reinterpret_cast<float4*>(&Bs[k][tx * 8]);
            float4 b1 = *reinterpret_cast<float4*>(&Bs[k][tx * 8 + 4]);
            float a[8] = {a0.x, a0.y, a0.z, a0.w, a1.x, a1.y, a1.z, a1.w};
            float b[8] = {b0.x, b0.y, b0.z, b0.w, b1.x, b1.y, b1.z, b1.w};
            #pragma unroll
            for (int i = 0; i < 8; i++)
                #pragma unroll
                for (int j = 0; j < 8; j++)
                    acc[i][j] += a[i] * b[j];
        }
        __syncthreads();
    }

    #pragma unroll
    for (int ii = 0; ii < 8; ii++) {
        const int row = row0 + ty * 8 + ii;
        if (row < M) {
            float* cp = C + (size_t)row * 768 + ct * 128 + tx * 8;
            *reinterpret_cast<float4*>(cp) =
                make_float4(acc[ii][0], acc[ii][1], acc[ii][2], acc[ii][3]);
            *reinterpret_cast<float4*>(cp + 4) =
                make_float4(acc[ii][4], acc[ii][5], acc[ii][6], acc[ii][7]);
        }
    }
}

// ---------------- el/er: warp per (node, etype) ----------------
__global__ __launch_bounds__(256) void eler_kernel(
    const float* __restrict__ h, const float* __restrict__ al,
    const float* __restrict__ ar, float* __restrict__ el,
    float* __restrict__ er, int n)
{
    const int w    = (blockIdx.x * blockDim.x + threadIdx.x) >> 5;
    const int lane = threadIdx.x & 31;
    if (w >= n * 3) return;
    const int i = w / 3, t = w % 3;

    const float* hp  = h + (size_t)i * 768 + t * 256;
    const float* alp = al + t * 256;
    const float* arp = ar + t * 256;

    float se[4] = {0.f, 0.f, 0.f, 0.f};
    float sr[4] = {0.f, 0.f, 0.f, 0.f};
    #pragma unroll
    for (int k = 0; k < 8; k++) {
        const int d = lane + 32 * k;
        const float v = hp[d];
        se[k >> 1] += v * alp[d];
        sr[k >> 1] += v * arp[d];
    }
    #pragma unroll
    for (int o = 16; o > 0; o >>= 1) {
        #pragma unroll
        for (int q = 0; q < 4; q++) {
            se[q] += __shfl_xor_sync(0xffffffffu, se[q], o);
            sr[q] += __shfl_xor_sync(0xffffffffu, sr[q], o);
        }
    }
    if (lane == 0) {
        #pragma unroll
        for (int q = 0; q < 4; q++) {
            el[(size_t)i * 12 + t * 4 + q] = se[q];
            er[(size_t)i * 12 + t * 4 + q] = sr[q];
        }
    }
}

// ---------------- aggregation: block per node ----------------
__global__ __launch_bounds__(256) void agg_kernel(
    const float* __restrict__ h, const float* __restrict__ el,
    const float* __restrict__ er, const int* __restrict__ src,
    const float* __restrict__ bias, float* __restrict__ xout,
    int n, int do_elu)
{
    const int i   = blockIdx.x;
    const int tid = threadIdx.x;
    const int E   = n * 16;

    __shared__ int   s_src[48];
    __shared__ float s_alpha[12][16];

    if (tid < 48) {
        const int t = tid >> 4, j = tid & 15;
        s_src[tid] = src[(size_t)t * E + i * 16 + j];
    }
    __syncthreads();

    if (tid < 12) {
        const int t = tid >> 2;
        const float eri = er[(size_t)i * 12 + tid];
        float e[16];
        float mx = -1e30f;
        #pragma unroll
        for (int j = 0; j < 16; j++) {
            const int s = s_src[t * 16 + j];
            float v = el[(size_t)s * 12 + tid] + eri;
            v = v > 0.f ? v : 0.2f * v;
            e[j] = v;
            mx = fmaxf(mx, v);
        }
        float sum = 0.f;
        #pragma unroll
        for (int j = 0; j < 16; j++) { e[j] = __expf(e[j] - mx); sum += e[j]; }
        const float inv = 1.0f / sum;
        #pragma unroll
        for (int j = 0; j < 16; j++) s_alpha[tid][j] = e[j] * inv;
    }
    __syncthreads();

    const int c  = tid;
    const int hd = c >> 6;
    float acc = 0.f;
    #pragma unroll
    for (int t = 0; t < 3; t++) {
        acc += bias[t * 256 + c];
        const float* hb = h + t * 256 + c;
        #pragma unroll
        for (int j = 0; j < 16; j++) {
            acc += s_alpha[t * 4 + hd][j] * hb[(size_t)s_src[t * 16 + j] * 768];
        }
    }
    acc *= (1.0f / 3.0f);
    if (do_elu) acc = acc > 0.f ? acc : (__expf(acc) - 1.0f);
    xout[(size_t)i * 256 + c] = acc;
}

// ---------------- layer-2 projection: warp per row, 6 outputs ----------------
__global__ __launch_bounds__(256) void gemm2_kernel(
    const float* __restrict__ X, const float* __restrict__ W2,
    float* __restrict__ h2, int n)
{
    const int w    = (blockIdx.x * blockDim.x + threadIdx.x) >> 5;
    const int lane = threadIdx.x & 31;
    if (w >= n) return;

    const float* xp = X + (size_t)w * 256;
    float s[6] = {0.f, 0.f, 0.f, 0.f, 0.f, 0.f};
    #pragma unroll
    for (int k = 0; k < 8; k++) {
        const int d = lane + 32 * k;
        const float x = xp[d];
        #pragma unroll
        for (int t = 0; t < 3; t++) {
            s[t * 2 + 0] += x * W2[t * 512 + d * 2 + 0];
            s[t * 2 + 1] += x * W2[t * 512 + d * 2 + 1];
        }
    }
    #pragma unroll
    for (int o = 16; o > 0; o >>= 1)
        #pragma unroll
        for (int q = 0; q < 6; q++)
            s[q] += __shfl_xor_sync(0xffffffffu, s[q], o);
    if (lane < 6) h2[(size_t)w * 6 + lane] = s[lane];
}

// ---------------- final: layer-2 attention + outputs ----------------
__global__ __launch_bounds__(128) void final_kernel(
    const float* __restrict__ h2, const float* __restrict__ al2,
    const float* __restrict__ ar2, const float* __restrict__ b2,
    const int* __restrict__ src, float* __restrict__ out,
    int n, int out_size)
{
    const int i = blockIdx.x * blockDim.x + threadIdx.x;
    if (i >= n) return;
    const int E = n * 16;

    float acc0 = 0.f, acc1 = 0.f;
    for (int t = 0; t < 3; t++) {
        const float hi0 = h2[(size_t)i * 6 + t * 2 + 0];
        const float hi1 = h2[(size_t)i * 6 + t * 2 + 1];
        const float eri = hi0 * ar2[t * 2 + 0] + hi1 * ar2[t * 2 + 1];
        const float a0 = al2[t * 2 + 0], a1 = al2[t * 2 + 1];

        float e[16], v0[16], v1[16];
        float mx = -1e30f;
        #pragma unroll
        for (int j = 0; j < 16; j++) {
            const int s = src[(size_t)t * E + i * 16 + j];
            const float p0 = h2[(size_t)s * 6 + t * 2 + 0];
            const float p1 = h2[(size_t)s * 6 + t * 2 + 1];
            v0[j] = p0; v1[j] = p1;
            float ev = p0 * a0 + p1 * a1 + eri;
            ev = ev > 0.f ? ev : 0.2f * ev;
            e[j] = ev;
            mx = fmaxf(mx, ev);
        }
        float sum = 0.f;
        #pragma unroll
        for (int j = 0; j < 16; j++) { e[j] = __expf(e[j] - mx); sum += e[j]; }
        const float inv = 1.0f / sum;
        float o0 = 0.f, o1 = 0.f;
        #pragma unroll
        for (int j = 0; j < 16; j++) { o0 += e[j] * v0[j]; o1 += e[j] * v1[j]; }
        acc0 += o0 * inv + b2[t * 2 + 0];
        acc1 += o1 * inv + b2[t * 2 + 1];
    }
    out[(size_t)i * 2 + 0] = acc0 * (1.0f / 3.0f);
    out[(size_t)i * 2 + 1] = acc1 * (1.0f / 3.0f);
    // second output: softmax over size-1 head axis == 1.0 everywhere
    if (out_size >= 4 * n) {
        out[(size_t)n * 2 + i * 2 + 0] = 1.0f;
        out[(size_t)n * 2 + i * 2 + 1] = 1.0f;
    }
}

// ---------------- launch ----------------
extern "C" void kernel_launch(void* const* d_in, const int* in_sizes, int n_in,
                              void* d_out, int out_size)
{
    const float* feat = (const float*)d_in[0];
    const float* W0   = (const float*)d_in[1];
    const float* al0  = (const float*)d_in[2];
    const float* ar0  = (const float*)d_in[3];
    const float* b0   = (const float*)d_in[4];
    const float* W1   = (const float*)d_in[5];
    const float* al1  = (const float*)d_in[6];
    const float* ar1  = (const float*)d_in[7];
    const float* b1   = (const float*)d_in[8];
    const float* W2   = (const float*)d_in[9];
    const float* al2  = (const float*)d_in[10];
    const float* ar2  = (const float*)d_in[11];
    const float* b2   = (const float*)d_in[12];
    const int*   src  = (const int*)d_in[13];
    float* out = (float*)d_out;

    const int n = in_sizes[0] / 128;   // 30000

    float *h, *x1, *x2, *el, *er, *h2;
    cudaGetSymbolAddress((void**)&h,  g_h);
    cudaGetSymbolAddress((void**)&x1, g_x1);
    cudaGetSymbolAddress((void**)&x2, g_x2);
    cudaGetSymbolAddress((void**)&el, g_el);
    cudaGetSymbolAddress((void**)&er, g_er);
    cudaGetSymbolAddress((void**)&h2, g_h2);

    const dim3 ggrid((n + BM - 1) / BM, 6);

    // layer 0
    sgemm_etype<<<ggrid, 256>>>(feat, W0, h, n, 128);
    eler_kernel<<<(n * 3 * 32 + 255) / 256, 256>>>(h, al0, ar0, el, er, n);
    agg_kernel<<<n, 256>>>(h, el, er, src, b0, x1, n, 1);

    // layer 1
    sgemm_etype<<<ggrid, 256>>>(x1, W1, h, n, 256);
    eler_kernel<<<(n * 3 * 32 + 255) / 256, 256>>>(h, al1, ar1, el, er, n);
    agg_kernel<<<n, 256>>>(h, el, er, src, b1, x2, n, 1);

    // layer 2
    gemm2_kernel<<<(n * 32 + 255) / 256, 256>>>(x2, W2, h2, n);
    final_kernel<<<(n + 127) / 128, 128>>>(h2, al2, ar2, b2, src, out, n, out_size);
}

// round 3
// speedup vs baseline: 1.1647x; 1.1647x over previous
#include <cuda_runtime.h>
#include <cuda_fp16.h>
#include <cstdint>

#define NMAX 30000

// ---------------- scratch (no allocation allowed) ----------------
__device__ __half g_h [NMAX * 768];   // projected feats fp16, [N][t][256]
__device__ float  g_x1[NMAX * 256];   // layer-0 output
__device__ float  g_x2[NMAX * 256];   // layer-1 output
__device__ float  g_el[NMAX * 12];    // [N][t][head]
__device__ float  g_er[NMAX * 12];
__device__ float  g_h2[NMAX * 6];     // layer-2 projected [N][t][2]

// ---------------- packed fp32x2 helpers (sm_103a) ----------------
#define FMA2(d, a, b, c) \
    asm("fma.rn.f32x2 %0, %1, %2, %3;" : "=l"(d) : "l"(a), "l"(b), "l"(c))
#define PACK2DUP(d, x) \
    asm("mov.b64 %0, {%1, %1};" : "=l"(d) : "r"(__float_as_uint(x)))

// ---------------- GEMM: C_fp16[N,768] = X[N,K] @ {W_t[K,256]} ----------------
// blockIdx.y in [0,6): 128-col tile. etype = y/2, within-etype colbase = (y&1)*128.
#define BM 128
#define BN 128
#define BK 16

__global__ __launch_bounds__(256, 2) void sgemm_etype(
    const float* __restrict__ X, const float* __restrict__ W,
    __half* __restrict__ C, int M, int K)
{
    __shared__ float As[BK][BM];
    __shared__ float Bs[BK][BN];

    const int tid  = threadIdx.x;
    const int row0 = blockIdx.x * BM;
    const int ct   = blockIdx.y;
    const int t    = ct >> 1;
    const int colbase = (ct & 1) * 128;
    const float* Wt = W + (size_t)t * K * 256;

    const int tx = tid & 15, ty = tid >> 4;

    // 8x8 fp32 accumulators packed as 8x4 f32x2
    unsigned long long acc[8][4];
    #pragma unroll
    for (int i = 0; i < 8; i++)
        #pragma unroll
        for (int j = 0; j < 4; j++) acc[i][j] = 0ull;

    const int arow = tid >> 1;            // 0..127
    const int ak8  = (tid & 1) * 8;       // 0 or 8
    const int bk   = tid >> 4;            // 0..15
    const int bc8  = (tid & 15) * 8;      // 0..120

    // prefetch tile 0 into registers
    float4 pa0 = make_float4(0.f, 0.f, 0.f, 0.f), pa1 = pa0, pb0, pb1;
    {
        const int gr = row0 + arow;
        if (gr < M) {
            pa0 = *reinterpret_cast<const float4*>(X + (size_t)gr * K + ak8);
            pa1 = *reinterpret_cast<const float4*>(X + (size_t)gr * K + ak8 + 4);
        }
        pb0 = *reinterpret_cast<const float4*>(Wt + (size_t)bk * 256 + colbase + bc8);
        pb1 = *reinterpret_cast<const float4*>(Wt + (size_t)bk * 256 + colbase + bc8 + 4);
    }

    for (int k0 = 0; k0 < K; k0 += BK) {
        // commit prefetched tile to shared
        As[ak8 + 0][arow] = pa0.x;  As[ak8 + 1][arow] = pa0.y;
        As[ak8 + 2][arow] = pa0.z;  As[ak8 + 3][arow] = pa0.w;
        As[ak8 + 4][arow] = pa1.x;  As[ak8 + 5][arow] = pa1.y;
        As[ak8 + 6][arow] = pa1.z;  As[ak8 + 7][arow] = pa1.w;
        *reinterpret_cast<float4*>(&Bs[bk][bc8])     = pb0;
        *reinterpret_cast<float4*>(&Bs[bk][bc8 + 4]) = pb1;
        __syncthreads();

        // prefetch next tile (overlaps with compute below)
        if (k0 + BK < K) {
            const int gr = row0 + arow;
            pa0 = make_float4(0.f, 0.f, 0.f, 0.f); pa1 = pa0;
            if (gr < M) {
                pa0 = *reinterpret_cast<const float4*>(X + (size_t)gr * K + k0 + BK + ak8);
                pa1 = *reinterpret_cast<const float4*>(X + (size_t)gr * K + k0 + BK + ak8 + 4);
            }
            pb0 = *reinterpret_cast<const float4*>(Wt + (size_t)(k0 + BK + bk) * 256 + colbase + bc8);
            pb1 = *reinterpret_cast<const float4*>(Wt + (size_t)(k0 + BK + bk) * 256 + colbase + bc8 + 4);
        }

        #pragma unroll
        for (int k = 0; k < BK; k++) {
            float4 a0 = *reinterpret_cast<float4*>(&As[k][ty * 8]);
            float4 a1 = *reinterpret_cast<float4*>(&As[k][ty * 8 + 4]);
            ulonglong2 bA = *reinterpret_cast<const ulonglong2*>(&Bs[k][tx * 8]);
            ulonglong2 bB = *reinterpret_cast<const ulonglong2*>(&Bs[k][tx * 8 + 4]);
            unsigned long long b[4] = {bA.x, bA.y, bB.x, bB.y};
            float av[8] = {a0.x, a0.y, a0.z, a0.w, a1.x, a1.y, a1.z, a1.w};
            #pragma unroll
            for (int i = 0; i < 8; i++) {
                unsigned long long ad;
                PACK2DUP(ad, av[i]);
                #pragma unroll
                for (int j = 0; j < 4; j++)
                    FMA2(acc[i][j], ad, b[j], acc[i][j]);
            }
        }
        __syncthreads();
    }

    // epilogue: unpack f32x2 pairs, convert to fp16, 16B stores
    #pragma unroll
    for (int i = 0; i < 8; i++) {
        const int row = row0 + ty * 8 + i;
        if (row < M) {
            __half2 hv[4];
            #pragma unroll
            for (int j = 0; j < 4; j++) {
                unsigned lo, hi;
                asm("mov.b64 {%0, %1}, %2;" : "=r"(lo), "=r"(hi) : "l"(acc[i][j]));
                __half2 p;
                p.x = __float2half_rn(__uint_as_float(lo));
                p.y = __float2half_rn(__uint_as_float(hi));
                hv[j] = p;
            }
            *reinterpret_cast<uint4*>(C + (size_t)row * 768 + ct * 128 + tx * 8) =
                *reinterpret_cast<uint4*>(hv);
        }
    }
}

// ---------------- el/er: warp per (node, etype), fp16 h ----------------
__global__ __launch_bounds__(256) void eler_kernel(
    const __half* __restrict__ h, const float* __restrict__ al,
    const float* __restrict__ ar, float* __restrict__ el,
    float* __restrict__ er, int n)
{
    const int w    = (blockIdx.x * blockDim.x + threadIdx.x) >> 5;
    const int lane = threadIdx.x & 31;
    if (w >= n * 3) return;
    const int i = w / 3, t = w % 3;

    const __half* hp = h + (size_t)i * 768 + t * 256;
    const float* alp = al + t * 256;
    const float* arp = ar + t * 256;

    float se[4] = {0.f, 0.f, 0.f, 0.f};
    float sr[4] = {0.f, 0.f, 0.f, 0.f};
    #pragma unroll
    for (int k = 0; k < 8; k++) {
        const int d = lane + 32 * k;
        const float v = __half2float(hp[d]);
        se[k >> 1] += v * alp[d];
        sr[k >> 1] += v * arp[d];
    }
    #pragma unroll
    for (int o = 16; o > 0; o >>= 1) {
        #pragma unroll
        for (int q = 0; q < 4; q++) {
            se[q] += __shfl_xor_sync(0xffffffffu, se[q], o);
            sr[q] += __shfl_xor_sync(0xffffffffu, sr[q], o);
        }
    }
    if (lane == 0) {
        #pragma unroll
        for (int q = 0; q < 4; q++) {
            el[(size_t)i * 12 + t * 4 + q] = se[q];
            er[(size_t)i * 12 + t * 4 + q] = sr[q];
        }
    }
}

// ---------------- aggregation: block per node, fp16 gathers ----------------
__global__ __launch_bounds__(256) void agg_kernel(
    const __half* __restrict__ h, const float* __restrict__ el,
    const float* __restrict__ er, const int* __restrict__ src,
    const float* __restrict__ bias, float* __restrict__ xout,
    int n, int do_elu)
{
    const int i   = blockIdx.x;
    const int tid = threadIdx.x;
    const int E   = n * 16;

    __shared__ int   s_src[48];
    __shared__ float s_alpha[12][16];

    if (tid < 48) {
        const int t = tid >> 4, j = tid & 15;
        s_src[tid] = src[(size_t)t * E + i * 16 + j];
    }
    __syncthreads();

    if (tid < 12) {
        const int t = tid >> 2;
        const float eri = er[(size_t)i * 12 + tid];
        float e[16];
        float mx = -1e30f;
        #pragma unroll
        for (int j = 0; j < 16; j++) {
            const int s = s_src[t * 16 + j];
            float v = el[(size_t)s * 12 + tid] + eri;
            v = v > 0.f ? v : 0.2f * v;
            e[j] = v;
            mx = fmaxf(mx, v);
        }
        float sum = 0.f;
        #pragma unroll
        for (int j = 0; j < 16; j++) { e[j] = __expf(e[j] - mx); sum += e[j]; }
        const float inv = 1.0f / sum;
        #pragma unroll
        for (int j = 0; j < 16; j++) s_alpha[tid][j] = e[j] * inv;
    }
    __syncthreads();

    const int c  = tid;
    const int hd = c >> 6;
    float acc = 0.f;
    #pragma unroll
    for (int t = 0; t < 3; t++) {
        acc += bias[t * 256 + c];
        const __half* hb = h + t * 256 + c;
        #pragma unroll
        for (int j = 0; j < 16; j++) {
            acc += s_alpha[t * 4 + hd][j] *
                   __half2float(hb[(size_t)s_src[t * 16 + j] * 768]);
        }
    }
    acc *= (1.0f / 3.0f);
    if (do_elu) acc = acc > 0.f ? acc : (__expf(acc) - 1.0f);
    xout[(size_t)i * 256 + c] = acc;
}

// ---------------- layer-2 projection: warp per row, 6 outputs ----------------
__global__ __launch_bounds__(256) void gemm2_kernel(
    const float* __restrict__ X, const float* __restrict__ W2,
    float* __restrict__ h2, int n)
{
    const int w    = (blockIdx.x * blockDim.x + threadIdx.x) >> 5;
    const int lane = threadIdx.x & 31;
    if (w >= n) return;

    const float* xp = X + (size_t)w * 256;
    float s[6] = {0.f, 0.f, 0.f, 0.f, 0.f, 0.f};
    #pragma unroll
    for (int k = 0; k < 8; k++) {
        const int d = lane + 32 * k;
        const float x = xp[d];
        #pragma unroll
        for (int t = 0; t < 3; t++) {
            s[t * 2 + 0] += x * W2[t * 512 + d * 2 + 0];
            s[t * 2 + 1] += x * W2[t * 512 + d * 2 + 1];
        }
    }
    #pragma unroll
    for (int o = 16; o > 0; o >>= 1)
        #pragma unroll
        for (int q = 0; q < 6; q++)
            s[q] += __shfl_xor_sync(0xffffffffu, s[q], o);
    if (lane < 6) h2[(size_t)w * 6 + lane] = s[lane];
}

// ---------------- final: layer-2 attention + outputs ----------------
__global__ __launch_bounds__(128) void final_kernel(
    const float* __restrict__ h2, const float* __restrict__ al2,
    const float* __restrict__ ar2, const float* __restrict__ b2,
    const int* __restrict__ src, float* __restrict__ out,
    int n, int out_size)
{
    const int i = blockIdx.x * blockDim.x + threadIdx.x;
    if (i >= n) return;
    const int E = n * 16;

    float acc0 = 0.f, acc1 = 0.f;
    for (int t = 0; t < 3; t++) {
        const float hi0 = h2[(size_t)i * 6 + t * 2 + 0];
        const float hi1 = h2[(size_t)i * 6 + t * 2 + 1];
        const float eri = hi0 * ar2[t * 2 + 0] + hi1 * ar2[t * 2 + 1];
        const float a0 = al2[t * 2 + 0], a1 = al2[t * 2 + 1];

        float e[16], v0[16], v1[16];
        float mx = -1e30f;
        #pragma unroll
        for (int j = 0; j < 16; j++) {
            const int s = src[(size_t)t * E + i * 16 + j];
            const float p0 = h2[(size_t)s * 6 + t * 2 + 0];
            const float p1 = h2[(size_t)s * 6 + t * 2 + 1];
            v0[j] = p0; v1[j] = p1;
            float ev = p0 * a0 + p1 * a1 + eri;
            ev = ev > 0.f ? ev : 0.2f * ev;
            e[j] = ev;
            mx = fmaxf(mx, ev);
        }
        float sum = 0.f;
        #pragma unroll
        for (int j = 0; j < 16; j++) { e[j] = __expf(e[j] - mx); sum += e[j]; }
        const float inv = 1.0f / sum;
        float o0 = 0.f, o1 = 0.f;
        #pragma unroll
        for (int j = 0; j < 16; j++) { o0 += e[j] * v0[j]; o1 += e[j] * v1[j]; }
        acc0 += o0 * inv + b2[t * 2 + 0];
        acc1 += o1 * inv + b2[t * 2 + 1];
    }
    out[(size_t)i * 2 + 0] = acc0 * (1.0f / 3.0f);
    out[(size_t)i * 2 + 1] = acc1 * (1.0f / 3.0f);
    // second output: softmax over size-1 head axis == 1.0 everywhere
    if (out_size >= 4 * n) {
        out[(size_t)n * 2 + i * 2 + 0] = 1.0f;
        out[(size_t)n * 2 + i * 2 + 1] = 1.0f;
    }
}

// ---------------- launch ----------------
extern "C" void kernel_launch(void* const* d_in, const int* in_sizes, int n_in,
                              void* d_out, int out_size)
{
    const float* feat = (const float*)d_in[0];
    const float* W0   = (const float*)d_in[1];
    const float* al0  = (const float*)d_in[2];
    const float* ar0  = (const float*)d_in[3];
    const float* b0   = (const float*)d_in[4];
    const float* W1   = (const float*)d_in[5];
    const float* al1  = (const float*)d_in[6];
    const float* ar1  = (const float*)d_in[7];
    const float* b1   = (const float*)d_in[8];
    const float* W2   = (const float*)d_in[9];
    const float* al2  = (const float*)d_in[10];
    const float* ar2  = (const float*)d_in[11];
    const float* b2   = (const float*)d_in[12];
    const int*   src  = (const int*)d_in[13];
    float* out = (float*)d_out;

    const int n = in_sizes[0] / 128;   // 30000

    __half *h;
    float *x1, *x2, *el, *er, *h2;
    cudaGetSymbolAddress((void**)&h,  g_h);
    cudaGetSymbolAddress((void**)&x1, g_x1);
    cudaGetSymbolAddress((void**)&x2, g_x2);
    cudaGetSymbolAddress((void**)&el, g_el);
    cudaGetSymbolAddress((void**)&er, g_er);
    cudaGetSymbolAddress((void**)&h2, g_h2);

    const dim3 ggrid((n + BM - 1) / BM, 6);

    // layer 0
    sgemm_etype<<<ggrid, 256>>>(feat, W0, h, n, 128);
    eler_kernel<<<(n * 3 * 32 + 255) / 256, 256>>>(h, al0, ar0, el, er, n);
    agg_kernel<<<n, 256>>>(h, el, er, src, b0, x1, n, 1);

    // layer 1
    sgemm_etype<<<ggrid, 256>>>(x1, W1, h, n, 256);
    eler_kernel<<<(n * 3 * 32 + 255) / 256, 256>>>(h, al1, ar1, el, er, n);
    agg_kernel<<<n, 256>>>(h, el, er, src, b1, x2, n, 1);

    // layer 2
    gemm2_kernel<<<(n * 32 + 255) / 256, 256>>>(x2, W2, h2, n);
    final_kernel<<<(n + 127) / 128, 128>>>(h2, al2, ar2, b2, src, out, n, out_size);
}

// round 4
// speedup vs baseline: 1.8432x; 1.5826x over previous
#include <cuda_runtime.h>
#include <cuda_fp16.h>
#include <mma.h>
#include <cstdint>

using namespace nvcuda;

#define NMAX 30000

// ---------------- scratch (no allocation allowed) ----------------
__device__ __half g_featH[NMAX * 128];     // fp16 copy of input feats
__device__ __half g_w0h[3 * 128 * 256];    // fp16 W0
__device__ __half g_w1h[3 * 256 * 256];    // fp16 W1
__device__ __half g_h [NMAX * 768];        // projected feats fp16, [N][t][256]
__device__ __half g_x1h[NMAX * 256];       // layer-0 output (fp16)
__device__ __half g_x2h[NMAX * 256];       // layer-1 output (fp16)
__device__ float  g_el[NMAX * 12];         // [N][t][head]
__device__ float  g_er[NMAX * 12];
__device__ float  g_h2[NMAX * 6];          // layer-2 projected [N][t][2]

// ---------------- fp32 -> fp16 conversion (vectorized) ----------------
__global__ __launch_bounds__(256) void f2h4(
    const float* __restrict__ in, __half* __restrict__ out, int n4)
{
    const int i = blockIdx.x * blockDim.x + threadIdx.x;
    if (i < n4) {
        float4 v = reinterpret_cast<const float4*>(in)[i];
        __half2 a = __floats2half2_rn(v.x, v.y);
        __half2 b = __floats2half2_rn(v.z, v.w);
        reinterpret_cast<__half2*>(out)[2 * i + 0] = a;
        reinterpret_cast<__half2*>(out)[2 * i + 1] = b;
    }
}

// ---------------- HMMA GEMM: C_fp16[N,768] = X_fp16[N,K] @ {W_t_fp16[K,256]} ----
// blockIdx.y in [0,6): etype = y/2, within-etype colbase = (y&1)*128.
// CTA tile 128x128, 8 warps in 4x2 layout, warp tile 32x64 (2x4 wmma frags).
#define BM 128
#define BN 128
#define BKH 32
#define APAD 16   // As row = 48 halfs = 96B (mult of 16B for wmma ldm)
#define BPAD 16   // Bs row = 144 halfs = 288B

__global__ __launch_bounds__(256, 2) void hgemm(
    const __half* __restrict__ X, const __half* __restrict__ W,
    __half* __restrict__ C, int M, int K)
{
    __shared__ __half As[BM][BKH + APAD];
    __shared__ __half Bs[BKH][BN + BPAD];

    const int tid  = threadIdx.x;
    const int wid  = tid >> 5;
    const int lane = tid & 31;
    const int row0 = blockIdx.x * BM;
    const int ct   = blockIdx.y;
    const int t    = ct >> 1;
    const int colbase = (ct & 1) * 128;
    const __half* Wt = W + (size_t)t * K * 256;

    const int wm = wid >> 1;   // 0..3 (32-row strip)
    const int wn = wid & 1;    // 0..1 (64-col strip)

    wmma::fragment<wmma::accumulator, 16, 16, 16, float> acc[2][4];
    #pragma unroll
    for (int i = 0; i < 2; i++)
        #pragma unroll
        for (int j = 0; j < 4; j++) wmma::fill_fragment(acc[i][j], 0.0f);

    const int ar = tid >> 1;          // 0..127
    const int as = (tid & 1) * 16;    // 0 or 16
    const int br = tid >> 3;          // 0..31
    const int bs = (tid & 7) * 16;    // 0..112

    for (int k0 = 0; k0 < K; k0 += BKH) {
        // stage A (zero-fill OOB rows)
        uint4 v0 = make_uint4(0u, 0u, 0u, 0u), v1 = v0;
        if (row0 + ar < M) {
            const __half* xp = X + (size_t)(row0 + ar) * K + k0 + as;
            v0 = *reinterpret_cast<const uint4*>(xp);
            v1 = *reinterpret_cast<const uint4*>(xp + 8);
        }
        *reinterpret_cast<uint4*>(&As[ar][as])     = v0;
        *reinterpret_cast<uint4*>(&As[ar][as + 8]) = v1;

        // stage B
        const __half* wp = Wt + (size_t)(k0 + br) * 256 + colbase + bs;
        *reinterpret_cast<uint4*>(&Bs[br][bs])     = *reinterpret_cast<const uint4*>(wp);
        *reinterpret_cast<uint4*>(&Bs[br][bs + 8]) = *reinterpret_cast<const uint4*>(wp + 8);

        __syncthreads();

        #pragma unroll
        for (int kk = 0; kk < BKH; kk += 16) {
            wmma::fragment<wmma::matrix_a, 16, 16, 16, __half, wmma::row_major> af[2];
            wmma::fragment<wmma::matrix_b, 16, 16, 16, __half, wmma::row_major> bf[4];
            #pragma unroll
            for (int i = 0; i < 2; i++)
                wmma::load_matrix_sync(af[i], &As[wm * 32 + i * 16][kk], BKH + APAD);
            #pragma unroll
            for (int j = 0; j < 4; j++)
                wmma::load_matrix_sync(bf[j], &Bs[kk][wn * 64 + j * 16], BN + BPAD);
            #pragma unroll
            for (int i = 0; i < 2; i++)
                #pragma unroll
                for (int j = 0; j < 4; j++)
                    wmma::mma_sync(acc[i][j], af[i], bf[j], acc[i][j]);
        }
        __syncthreads();
    }

    // epilogue: per-warp smem patch -> fp16 -> guarded 16B global stores
    float* patch = reinterpret_cast<float*>(&As[0][0]) + wid * 256;  // 1KB/warp
    const int pr = lane >> 1;          // 0..15 row in patch
    const int pc = (lane & 1) * 8;     // 0 or 8

    #pragma unroll
    for (int i = 0; i < 2; i++) {
        #pragma unroll
        for (int j = 0; j < 4; j++) {
            wmma::store_matrix_sync(patch, acc[i][j], 16, wmma::mem_row_major);
            __syncwarp();
            const int grow = row0 + wm * 32 + i * 16 + pr;
            if (grow < M) {
                __half2 hv[4];
                #pragma unroll
                for (int q = 0; q < 4; q++)
                    hv[q] = __floats2half2_rn(patch[pr * 16 + pc + 2 * q],
                                              patch[pr * 16 + pc + 2 * q + 1]);
                *reinterpret_cast<uint4*>(
                    C + (size_t)grow * 768 + ct * 128 + wn * 64 + j * 16 + pc) =
                    *reinterpret_cast<uint4*>(hv);
            }
            __syncwarp();
        }
    }
}

// ---------------- el/er: warp per (node, etype), fp16 h ----------------
__global__ __launch_bounds__(256) void eler_kernel(
    const __half* __restrict__ h, const float* __restrict__ al,
    const float* __restrict__ ar, float* __restrict__ el,
    float* __restrict__ er, int n)
{
    const int w    = (blockIdx.x * blockDim.x + threadIdx.x) >> 5;
    const int lane = threadIdx.x & 31;
    if (w >= n * 3) return;
    const int i = w / 3, t = w % 3;

    const __half* hp = h + (size_t)i * 768 + t * 256;
    const float* alp = al + t * 256;
    const float* arp = ar + t * 256;

    float se[4] = {0.f, 0.f, 0.f, 0.f};
    float sr[4] = {0.f, 0.f, 0.f, 0.f};
    #pragma unroll
    for (int k = 0; k < 8; k++) {
        const int d = lane + 32 * k;
        const float v = __half2float(hp[d]);
        se[k >> 1] += v * alp[d];
        sr[k >> 1] += v * arp[d];
    }
    #pragma unroll
    for (int o = 16; o > 0; o >>= 1) {
        #pragma unroll
        for (int q = 0; q < 4; q++) {
            se[q] += __shfl_xor_sync(0xffffffffu, se[q], o);
            sr[q] += __shfl_xor_sync(0xffffffffu, sr[q], o);
        }
    }
    if (lane == 0) {
        #pragma unroll
        for (int q = 0; q < 4; q++) {
            el[(size_t)i * 12 + t * 4 + q] = se[q];
            er[(size_t)i * 12 + t * 4 + q] = sr[q];
        }
    }
}

// ---------------- aggregation: block per node, fp16 gathers, fp16 out -------
__global__ __launch_bounds__(256) void agg_kernel(
    const __half* __restrict__ h, const float* __restrict__ el,
    const float* __restrict__ er, const int* __restrict__ src,
    const float* __restrict__ bias, __half* __restrict__ xout,
    int n)
{
    const int i   = blockIdx.x;
    const int tid = threadIdx.x;
    const int E   = n * 16;

    __shared__ int   s_src[48];
    __shared__ float s_alpha[12][16];

    if (tid < 48) {
        const int t = tid >> 4, j = tid & 15;
        s_src[tid] = src[(size_t)t * E + i * 16 + j];
    }
    __syncthreads();

    if (tid < 12) {
        const int t = tid >> 2;
        const float eri = er[(size_t)i * 12 + tid];
        float e[16];
        float mx = -1e30f;
        #pragma unroll
        for (int j = 0; j < 16; j++) {
            const int s = s_src[t * 16 + j];
            float v = el[(size_t)s * 12 + tid] + eri;
            v = v > 0.f ? v : 0.2f * v;
            e[j] = v;
            mx = fmaxf(mx, v);
        }
        float sum = 0.f;
        #pragma unroll
        for (int j = 0; j < 16; j++) { e[j] = __expf(e[j] - mx); sum += e[j]; }
        const float inv = 1.0f / sum;
        #pragma unroll
        for (int j = 0; j < 16; j++) s_alpha[tid][j] = e[j] * inv;
    }
    __syncthreads();

    const int c  = tid;
    const int hd = c >> 6;
    float acc = 0.f;
    #pragma unroll
    for (int t = 0; t < 3; t++) {
        acc += bias[t * 256 + c];
        const __half* hb = h + t * 256 + c;
        #pragma unroll
        for (int j = 0; j < 16; j++) {
            acc += s_alpha[t * 4 + hd][j] *
                   __half2float(hb[(size_t)s_src[t * 16 + j] * 768]);
        }
    }
    acc *= (1.0f / 3.0f);
    acc = acc > 0.f ? acc : (__expf(acc) - 1.0f);   // ELU
    xout[(size_t)i * 256 + c] = __float2half_rn(acc);
}

// ---------------- layer-2 projection: warp per row, 6 outputs ----------------
__global__ __launch_bounds__(256) void gemm2_kernel(
    const __half* __restrict__ X, const float* __restrict__ W2,
    float* __restrict__ h2, int n)
{
    const int w    = (blockIdx.x * blockDim.x + threadIdx.x) >> 5;
    const int lane = threadIdx.x & 31;
    if (w >= n) return;

    const __half* xp = X + (size_t)w * 256;
    float s[6] = {0.f, 0.f, 0.f, 0.f, 0.f, 0.f};
    #pragma unroll
    for (int k = 0; k < 8; k++) {
        const int d = lane + 32 * k;
        const float x = __half2float(xp[d]);
        #pragma unroll
        for (int t = 0; t < 3; t++) {
            s[t * 2 + 0] += x * W2[t * 512 + d * 2 + 0];
            s[t * 2 + 1] += x * W2[t * 512 + d * 2 + 1];
        }
    }
    #pragma unroll
    for (int o = 16; o > 0; o >>= 1)
        #pragma unroll
        for (int q = 0; q < 6; q++)
            s[q] += __shfl_xor_sync(0xffffffffu, s[q], o);
    if (lane < 6) h2[(size_t)w * 6 + lane] = s[lane];
}

// ---------------- final: layer-2 attention + outputs ----------------
__global__ __launch_bounds__(128) void final_kernel(
    const float* __restrict__ h2, const float* __restrict__ al2,
    const float* __restrict__ ar2, const float* __restrict__ b2,
    const int* __restrict__ src, float* __restrict__ out,
    int n, int out_size)
{
    const int i = blockIdx.x * blockDim.x + threadIdx.x;
    if (i >= n) return;
    const int E = n * 16;

    float acc0 = 0.f, acc1 = 0.f;
    for (int t = 0; t < 3; t++) {
        const float hi0 = h2[(size_t)i * 6 + t * 2 + 0];
        const float hi1 = h2[(size_t)i * 6 + t * 2 + 1];
        const float eri = hi0 * ar2[t * 2 + 0] + hi1 * ar2[t * 2 + 1];
        const float a0 = al2[t * 2 + 0], a1 = al2[t * 2 + 1];

        float e[16], v0[16], v1[16];
        float mx = -1e30f;
        #pragma unroll
        for (int j = 0; j < 16; j++) {
            const int s = src[(size_t)t * E + i * 16 + j];
            const float p0 = h2[(size_t)s * 6 + t * 2 + 0];
            const float p1 = h2[(size_t)s * 6 + t * 2 + 1];
            v0[j] = p0; v1[j] = p1;
            float ev = p0 * a0 + p1 * a1 + eri;
            ev = ev > 0.f ? ev : 0.2f * ev;
            e[j] = ev;
            mx = fmaxf(mx, ev);
        }
        float sum = 0.f;
        #pragma unroll
        for (int j = 0; j < 16; j++) { e[j] = __expf(e[j] - mx); sum += e[j]; }
        const float inv = 1.0f / sum;
        float o0 = 0.f, o1 = 0.f;
        #pragma unroll
        for (int j = 0; j < 16; j++) { o0 += e[j] * v0[j]; o1 += e[j] * v1[j]; }
        acc0 += o0 * inv + b2[t * 2 + 0];
        acc1 += o1 * inv + b2[t * 2 + 1];
    }
    out[(size_t)i * 2 + 0] = acc0 * (1.0f / 3.0f);
    out[(size_t)i * 2 + 1] = acc1 * (1.0f / 3.0f);
    // second output: softmax over size-1 head axis == 1.0 everywhere
    if (out_size >= 4 * n) {
        out[(size_t)n * 2 + i * 2 + 0] = 1.0f;
        out[(size_t)n * 2 + i * 2 + 1] = 1.0f;
    }
}

// ---------------- launch ----------------
extern "C" void kernel_launch(void* const* d_in, const int* in_sizes, int n_in,
                              void* d_out, int out_size)
{
    const float* feat = (const float*)d_in[0];
    const float* W0   = (const float*)d_in[1];
    const float* al0  = (const float*)d_in[2];
    const float* ar0  = (const float*)d_in[3];
    const float* b0   = (const float*)d_in[4];
    const float* W1   = (const float*)d_in[5];
    const float* al1  = (const float*)d_in[6];
    const float* ar1  = (const float*)d_in[7];
    const float* b1   = (const float*)d_in[8];
    const float* W2   = (const float*)d_in[9];
    const float* al2  = (const float*)d_in[10];
    const float* ar2  = (const float*)d_in[11];
    const float* b2   = (const float*)d_in[12];
    const int*   src  = (const int*)d_in[13];
    float* out = (float*)d_out;

    const int n = in_sizes[0] / 128;   // 30000

    __half *featH, *w0h, *w1h, *h, *x1h, *x2h;
    float *el, *er, *h2;
    cudaGetSymbolAddress((void**)&featH, g_featH);
    cudaGetSymbolAddress((void**)&w0h,   g_w0h);
    cudaGetSymbolAddress((void**)&w1h,   g_w1h);
    cudaGetSymbolAddress((void**)&h,     g_h);
    cudaGetSymbolAddress((void**)&x1h,   g_x1h);
    cudaGetSymbolAddress((void**)&x2h,   g_x2h);
    cudaGetSymbolAddress((void**)&el,    g_el);
    cudaGetSymbolAddress((void**)&er,    g_er);
    cudaGetSymbolAddress((void**)&h2,    g_h2);

    const dim3 ggrid((n + BM - 1) / BM, 6);

    // fp16 conversions (weights + input feats)
    const int nf4 = n * 128 / 4;
    f2h4<<<(nf4 + 255) / 256, 256>>>(feat, featH, nf4);
    f2h4<<<(3 * 128 * 256 / 4 + 255) / 256, 256>>>(W0, w0h, 3 * 128 * 256 / 4);
    f2h4<<<(3 * 256 * 256 / 4 + 255) / 256, 256>>>(W1, w1h, 3 * 256 * 256 / 4);

    // layer 0
    hgemm<<<ggrid, 256>>>(featH, w0h, h, n, 128);
    eler_kernel<<<(n * 3 * 32 + 255) / 256, 256>>>(h, al0, ar0, el, er, n);
    agg_kernel<<<n, 256>>>(h, el, er, src, b0, x1h, n);

    // layer 1
    hgemm<<<ggrid, 256>>>(x1h, w1h, h, n, 256);
    eler_kernel<<<(n * 3 * 32 + 255) / 256, 256>>>(h, al1, ar1, el, er, n);
    agg_kernel<<<n, 256>>>(h, el, er, src, b1, x2h, n);

    // layer 2
    gemm2_kernel<<<(n * 32 + 255) / 256, 256>>>(x2h, W2, h2, n);
    final_kernel<<<(n + 127) / 128, 128>>>(h2, al2, ar2, b2, src, out, n, out_size);
}